// round 1
// baseline (speedup 1.0000x reference)
#include <cuda_runtime.h>
#include <cstdint>

// ---------------------------------------------------------------------------
// Fused attention block, fp32 baseline:
//   q = x@wq + bq ; k = x@wk + bk ; v = x@wv + bv
//   scores = 32 * q @ k^T   (per batch)
//   p = softmax(scores)     (written to d_out p_attn region)
//   ctx = p @ v
//   out = ctx @ wp + bp
// Shapes: B=4, S=2048, D=1024. M_total = 8192. All tile-divisible by 128.
// ---------------------------------------------------------------------------

#define BM 128
#define BN 128
#define BK 16
#define PAD 4

static const long long MQ = 8192LL * 1024LL;       // q/k/v/ctx elements
static const long long OUT_ELEMS = 8192LL * 1024LL;
static const long long PATTN_ELEMS = 4LL * 2048LL * 2048LL;

__device__ float g_q[8192 * 1024];
__device__ float g_k[8192 * 1024];
__device__ float g_v[8192 * 1024];
__device__ float g_ctx[8192 * 1024];
__device__ float g_scores_fallback[4 * 2048 * 2048];  // only if out lacks p_attn

// Tiled SGEMM: C[M,N] = alpha * A @ op(B) (+ bias). A row-major [M,K].
// TRANSB=false: B row-major [K,N].  TRANSB=true: B row-major [N,K] (C=A@B^T).
// blockIdx.z selects batch via strides.
template <bool TRANSB, bool HASBIAS>
__global__ void __launch_bounds__(256, 2) sgemm_kernel(
    const float* __restrict__ Ag, const float* __restrict__ Bg,
    const float* __restrict__ bias, float* __restrict__ Cg,
    int M, int N, int K, float alpha,
    long long sA, long long sB, long long sC)
{
    const float* A = Ag + (long long)blockIdx.z * sA;
    const float* B = Bg + (long long)blockIdx.z * sB;
    float* C = Cg + (long long)blockIdx.z * sC;

    __shared__ float As[BK][BM + PAD];
    __shared__ float Bs[BK][BN + PAD];

    const int tid = threadIdx.x;
    const int tx = tid & 15;   // 0..15 -> column groups
    const int ty = tid >> 4;   // 0..15 -> row groups

    const int row0 = blockIdx.y * BM;
    const int col0 = blockIdx.x * BN;

    const int a_r = tid >> 2;          // 0..63 (two passes: +64)
    const int a_c = (tid & 3) << 2;    // 0,4,8,12
    const int b_r = tid >> 5;          // 0..7  (two passes: +8)
    const int b_c = (tid & 31) << 2;   // 0..124

    float acc[8][8];
#pragma unroll
    for (int i = 0; i < 8; i++)
#pragma unroll
        for (int j = 0; j < 8; j++) acc[i][j] = 0.f;

    for (int k0 = 0; k0 < K; k0 += BK) {
        // --- load A tile (BM x BK), store transposed to As[k][m] ---
#pragma unroll
        for (int p = 0; p < 2; p++) {
            int r = a_r + p * 64;
            float4 t = *(const float4*)(A + (long long)(row0 + r) * K + k0 + a_c);
            As[a_c + 0][r] = t.x;
            As[a_c + 1][r] = t.y;
            As[a_c + 2][r] = t.z;
            As[a_c + 3][r] = t.w;
        }
        // --- load B tile ---
        if (TRANSB) {
            // B is [N,K]; tile rows are N. Store transposed: Bs[k][n]=B[n][k].
#pragma unroll
            for (int p = 0; p < 2; p++) {
                int r = a_r + p * 64;  // n within tile
                float4 t = *(const float4*)(B + (long long)(col0 + r) * K + k0 + a_c);
                Bs[a_c + 0][r] = t.x;
                Bs[a_c + 1][r] = t.y;
                Bs[a_c + 2][r] = t.z;
                Bs[a_c + 3][r] = t.w;
            }
        } else {
            // B is [K,N]; direct copy Bs[k][n].
#pragma unroll
            for (int p = 0; p < 2; p++) {
                int r = b_r + p * 8;
                *(float4*)&Bs[r][b_c] =
                    *(const float4*)(B + (long long)(k0 + r) * N + col0 + b_c);
            }
        }
        __syncthreads();

#pragma unroll
        for (int k = 0; k < BK; k++) {
            float a_f[8], b_f[8];
            *(float4*)&a_f[0] = *(const float4*)&As[k][ty * 4];
            *(float4*)&a_f[4] = *(const float4*)&As[k][64 + ty * 4];
            *(float4*)&b_f[0] = *(const float4*)&Bs[k][tx * 4];
            *(float4*)&b_f[4] = *(const float4*)&Bs[k][64 + tx * 4];
#pragma unroll
            for (int i = 0; i < 8; i++)
#pragma unroll
                for (int j = 0; j < 8; j++)
                    acc[i][j] = fmaf(a_f[i], b_f[j], acc[i][j]);
        }
        __syncthreads();
    }

    // --- epilogue ---
#pragma unroll
    for (int i = 0; i < 8; i++) {
        int r = row0 + ((i < 4) ? (ty * 4 + i) : (64 + ty * 4 + (i - 4)));
#pragma unroll
        for (int half = 0; half < 2; half++) {
            int c = col0 + ((half == 0) ? (tx * 4) : (64 + tx * 4));
            float4 o;
            o.x = acc[i][half * 4 + 0] * alpha;
            o.y = acc[i][half * 4 + 1] * alpha;
            o.z = acc[i][half * 4 + 2] * alpha;
            o.w = acc[i][half * 4 + 3] * alpha;
            if (HASBIAS) {
                o.x += bias[c + 0];
                o.y += bias[c + 1];
                o.z += bias[c + 2];
                o.w += bias[c + 3];
            }
            *(float4*)(C + (long long)r * N + c) = o;
        }
    }
}

// In-place softmax over rows of length 2048. One block (256 thr) per row.
__global__ void __launch_bounds__(256) softmax2048_kernel(float* __restrict__ p)
{
    float* row = p + (long long)blockIdx.x * 2048;
    const int tid = threadIdx.x;

    float4 v0 = ((const float4*)row)[tid];
    float4 v1 = ((const float4*)row)[tid + 256];

    float m = fmaxf(fmaxf(fmaxf(v0.x, v0.y), fmaxf(v0.z, v0.w)),
                    fmaxf(fmaxf(v1.x, v1.y), fmaxf(v1.z, v1.w)));

    __shared__ float red[8];
#pragma unroll
    for (int o = 16; o; o >>= 1) m = fmaxf(m, __shfl_xor_sync(0xffffffffu, m, o));
    if ((tid & 31) == 0) red[tid >> 5] = m;
    __syncthreads();
    m = red[0];
#pragma unroll
    for (int i = 1; i < 8; i++) m = fmaxf(m, red[i]);
    __syncthreads();  // red reuse safety

    v0.x = expf(v0.x - m); v0.y = expf(v0.y - m);
    v0.z = expf(v0.z - m); v0.w = expf(v0.w - m);
    v1.x = expf(v1.x - m); v1.y = expf(v1.y - m);
    v1.z = expf(v1.z - m); v1.w = expf(v1.w - m);

    float s = (v0.x + v0.y) + (v0.z + v0.w) + (v1.x + v1.y) + (v1.z + v1.w);
#pragma unroll
    for (int o = 16; o; o >>= 1) s += __shfl_xor_sync(0xffffffffu, s, o);
    if ((tid & 31) == 0) red[tid >> 5] = s;
    __syncthreads();
    s = ((red[0] + red[1]) + (red[2] + red[3])) +
        ((red[4] + red[5]) + (red[6] + red[7]));
    float inv = 1.0f / s;

    v0.x *= inv; v0.y *= inv; v0.z *= inv; v0.w *= inv;
    v1.x *= inv; v1.y *= inv; v1.z *= inv; v1.w *= inv;

    ((float4*)row)[tid] = v0;
    ((float4*)row)[tid + 256] = v1;
}

extern "C" void kernel_launch(void* const* d_in, const int* in_sizes, int n_in,
                              void* d_out, int out_size)
{
    const float* x  = (const float*)d_in[0];
    const float* wq = (const float*)d_in[1];
    const float* bq = (const float*)d_in[2];
    const float* wk = (const float*)d_in[3];
    const float* bk = (const float*)d_in[4];
    const float* wv = (const float*)d_in[5];
    const float* bv = (const float*)d_in[6];
    const float* wp = (const float*)d_in[7];
    const float* bp = (const float*)d_in[8];

    float* out = (float*)d_out;

    float *q, *k, *v, *ctx, *scoresfb;
    cudaGetSymbolAddress((void**)&q, g_q);
    cudaGetSymbolAddress((void**)&k, g_k);
    cudaGetSymbolAddress((void**)&v, g_v);
    cudaGetSymbolAddress((void**)&ctx, g_ctx);
    cudaGetSymbolAddress((void**)&scoresfb, g_scores_fallback);

    // p_attn lives in d_out after `output` if the harness concatenates the
    // tuple (expected). Otherwise fall back to device-global scratch.
    float* pattn = (out_size >= (int)(OUT_ELEMS + PATTN_ELEMS))
                       ? (out + OUT_ELEMS)
                       : scoresfb;

    const float scale = 32.0f;  // sqrt(1024)

    // 1-3) QKV projections: [8192,1024] = x[8192,1024] @ w[1024,1024] + b
    dim3 gProj(1024 / BN, 8192 / BM, 1);
    sgemm_kernel<false, true><<<gProj, 256>>>(x, wq, bq, q, 8192, 1024, 1024, 1.f, 0, 0, 0);
    sgemm_kernel<false, true><<<gProj, 256>>>(x, wk, bk, k, 8192, 1024, 1024, 1.f, 0, 0, 0);
    sgemm_kernel<false, true><<<gProj, 256>>>(x, wv, bv, v, 8192, 1024, 1024, 1.f, 0, 0, 0);

    // 4) scores = 32 * q @ k^T per batch -> written directly into p_attn region
    dim3 gScores(2048 / BN, 2048 / BM, 4);
    sgemm_kernel<true, false><<<gScores, 256>>>(
        q, k, nullptr, pattn, 2048, 2048, 1024, scale,
        2048LL * 1024LL, 2048LL * 1024LL, 2048LL * 2048LL);

    // 5) softmax rows in place (8192 rows x 2048)
    softmax2048_kernel<<<8192, 256>>>(pattn);

    // 6) ctx = p @ v per batch: [2048,1024] = [2048,2048] @ [2048,1024]
    dim3 gCtx(1024 / BN, 2048 / BM, 4);
    sgemm_kernel<false, false><<<gCtx, 256>>>(
        pattn, v, nullptr, ctx, 2048, 1024, 2048, 1.f,
        2048LL * 2048LL, 2048LL * 1024LL, 2048LL * 1024LL);

    // 7) out = ctx @ wp + bp
    sgemm_kernel<false, true><<<gProj, 256>>>(ctx, wp, bp, out, 8192, 1024, 1024, 1.f, 0, 0, 0);
}

// round 3
// speedup vs baseline: 2.1845x; 2.1845x over previous
#include <cuda_runtime.h>
#include <cuda_fp16.h>
#include <cstdint>

// ============================================================================
// Fused attention block via mma.sync (HMMA, family-generic PTX — tcgen05 is
// rejected by this harness's compute_103 target). fp32 accuracy recovered by
// fp16 hi/lo split: x*y ~= xh*yh + xl*yh + xh*yl (fp32 accum), eps ~ 2^-21.
//
//   q = x@wq+bq ; k = x@wk+bk ; v = x@wv+bv
//   scores = 32 * q @ k^T (per batch) -> softmax -> p (d_out region)
//   ctx = p @ v ; out = ctx @ wp + bp
// B=4, S=2048, D=1024.
// ============================================================================

#define TOK 8192
#define DIM 1024
#define SEQ 2048
#define BATCH 4

static const long long OUT_ELEMS = (long long)TOK * DIM;
static const long long PATTN_ELEMS = (long long)BATCH * SEQ * SEQ;

// ---------------- device scratch ----------------
__device__ __half g_xhi[TOK * DIM], g_xlo[TOK * DIM];
__device__ __half g_wqThi[DIM * DIM], g_wqTlo[DIM * DIM];
__device__ __half g_wkThi[DIM * DIM], g_wkTlo[DIM * DIM];
__device__ __half g_wvThi[DIM * DIM], g_wvTlo[DIM * DIM];
__device__ __half g_wpThi[DIM * DIM], g_wpTlo[DIM * DIM];
__device__ __half g_qhi[TOK * DIM], g_qlo[TOK * DIM];
__device__ __half g_khi[TOK * DIM], g_klo[TOK * DIM];
__device__ float  g_v[TOK * DIM];
__device__ __half g_vThi[TOK * DIM], g_vTlo[TOK * DIM];   // [B][DIM][SEQ]
__device__ __half g_phi[BATCH * SEQ * SEQ], g_plo[BATCH * SEQ * SEQ];
__device__ __half g_ctxhi[TOK * DIM], g_ctxlo[TOK * DIM];
__device__ float  g_scores_fb[BATCH * SEQ * SEQ];

// ---------------- PTX helpers ----------------
__device__ __forceinline__ uint32_t smem_u32_f(const void* p) {
    uint32_t a;
    asm("{ .reg .u64 t; cvta.to.shared.u64 t, %1; cvt.u32.u64 %0, t; }"
        : "=r"(a) : "l"(p));
    return a;
}
__device__ __forceinline__ void cp16(uint32_t dst, const void* src) {
    asm volatile("cp.async.cg.shared.global [%0], [%1], 16;" :: "r"(dst), "l"(src));
}
__device__ __forceinline__ void cp_commit() { asm volatile("cp.async.commit_group;"); }
template <int N>
__device__ __forceinline__ void cp_wait() {
    asm volatile("cp.async.wait_group %0;" :: "n"(N));
}
__device__ __forceinline__ void ldm_x4(uint32_t r[4], uint32_t addr) {
    asm volatile("ldmatrix.sync.aligned.m8n8.x4.shared.b16 {%0,%1,%2,%3}, [%4];"
                 : "=r"(r[0]), "=r"(r[1]), "=r"(r[2]), "=r"(r[3]) : "r"(addr));
}
__device__ __forceinline__ void mma16816(float c[4], const uint32_t a[4],
                                         const uint32_t b0, const uint32_t b1) {
    asm volatile(
        "mma.sync.aligned.m16n8k16.row.col.f32.f16.f16.f32 "
        "{%0,%1,%2,%3},{%4,%5,%6,%7},{%8,%9},{%0,%1,%2,%3};"
        : "+f"(c[0]), "+f"(c[1]), "+f"(c[2]), "+f"(c[3])
        : "r"(a[0]), "r"(a[1]), "r"(a[2]), "r"(a[3]), "r"(b0), "r"(b1));
}

// smem tile geometry: 128 rows x 32 halfs, row pitch 80B (64B data + 16B pad)
#define PITCH 80u
#define TILE_B (128u * PITCH)            // 10240 B
#define T_AH 0u
#define T_AL TILE_B
#define T_BH (2u * TILE_B)
#define T_BL (3u * TILE_B)
#define STG  (4u * TILE_B)               // 40960 B per stage
#define SMEM_DYN (2 * 4 * 10240)         // 81920 B

// ============================================================================
// MMA GEMM: C[M,N] = alpha * (Ah+Al)[M,K] @ (Bh+Bl)[N,K]^T (+bias)
// Block tile 128x128, BK=32, 256 threads (8 warps, 4x2 warp grid).
// WF32: write fp32 to Cf. else: write hi/lo fp16 splits to Chi/Clo.
// ============================================================================
template <bool WF32, bool HASBIAS>
__global__ void __launch_bounds__(256) mma_gemm(
    const __half* __restrict__ Ah_g, const __half* __restrict__ Al_g,
    const __half* __restrict__ Bh_g, const __half* __restrict__ Bl_g,
    const float* __restrict__ bias,
    float* __restrict__ Cf, __half* __restrict__ Chi, __half* __restrict__ Clo,
    int N, int K, float alpha,
    long long sA, long long sB, long long sC)
{
    extern __shared__ char smem_raw[];
    const uint32_t base = smem_u32_f(smem_raw);

    const int tid = threadIdx.x;
    const int warp = tid >> 5, lane = tid & 31;
    const long long zb = blockIdx.z;
    const __half* Ah = Ah_g + zb * sA;
    const __half* Al = Al_g + zb * sA;
    const __half* Bh = Bh_g + zb * sB;
    const __half* Bl = Bl_g + zb * sB;

    const int row0 = blockIdx.y * 128;
    const int col0 = blockIdx.x * 128;

    // cp.async slots: 512 16B-chunks per tile; thread does 2 per tile.
    const int r_ld = tid >> 2;          // 0..63 (+64 on second pass)
    const int q_ld = tid & 3;           // 16B chunk within 64B row
    long long aOff[2], bOff[2];
    uint32_t dOff[2];
#pragma unroll
    for (int j = 0; j < 2; j++) {
        int r = r_ld + j * 64;
        aOff[j] = (long long)(row0 + r) * K + q_ld * 8;
        bOff[j] = (long long)(col0 + r) * K + q_ld * 8;
        dOff[j] = (uint32_t)r * PITCH + (uint32_t)q_ld * 16u;
    }

    // warp tiles: 4 (m) x 2 (n); warp tile 32(m) x 64(n)
    const int wm = warp & 3, wn = warp >> 2;
    const int m0 = wm * 32, n0 = wn * 64;
    // ldmatrix lane offsets
    const uint32_t aLane = (uint32_t)(lane & 15) * PITCH + (uint32_t)(lane >> 4) * 16u;
    const uint32_t bLane = (uint32_t)((lane & 7) + ((lane >> 4) << 3)) * PITCH +
                           (uint32_t)((lane >> 3) & 1) * 16u;

    float acc[2][8][4];
#pragma unroll
    for (int i = 0; i < 2; i++)
#pragma unroll
        for (int j = 0; j < 8; j++)
#pragma unroll
            for (int e = 0; e < 4; e++) acc[i][j][e] = 0.f;

    const int nk = K >> 5;   // BK = 32

    // prologue: stage 0
    {
        uint32_t sb = base;
#pragma unroll
        for (int j = 0; j < 2; j++) {
            cp16(sb + T_AH + dOff[j], Ah + aOff[j]);
            cp16(sb + T_AL + dOff[j], Al + aOff[j]);
            cp16(sb + T_BH + dOff[j], Bh + bOff[j]);
            cp16(sb + T_BL + dOff[j], Bl + bOff[j]);
        }
        cp_commit();
    }

    for (int i = 0; i < nk; i++) {
        if (i + 1 < nk) {
            uint32_t sb = base + (uint32_t)((i + 1) & 1) * STG;
            long long k0 = (long long)(i + 1) * 32;
#pragma unroll
            for (int j = 0; j < 2; j++) {
                cp16(sb + T_AH + dOff[j], Ah + aOff[j] + k0);
                cp16(sb + T_AL + dOff[j], Al + aOff[j] + k0);
                cp16(sb + T_BH + dOff[j], Bh + bOff[j] + k0);
                cp16(sb + T_BL + dOff[j], Bl + bOff[j] + k0);
            }
            cp_commit();
            cp_wait<1>();
        } else {
            cp_wait<0>();
        }
        __syncthreads();

        const uint32_t sb = base + (uint32_t)(i & 1) * STG;
#pragma unroll
        for (int ks = 0; ks < 2; ks++) {
            const uint32_t kb = (uint32_t)ks * 32u;  // 16 halfs = 32 B
            uint32_t ah[2][4], al[2][4], bh[4][4], bl[4][4];
#pragma unroll
            for (int mf = 0; mf < 2; mf++) {
                uint32_t ro = (uint32_t)(m0 + mf * 16) * PITCH + kb + aLane;
                ldm_x4(ah[mf], sb + T_AH + ro);
                ldm_x4(al[mf], sb + T_AL + ro);
            }
#pragma unroll
            for (int q = 0; q < 4; q++) {
                uint32_t ro = (uint32_t)(n0 + q * 16) * PITCH + kb + bLane;
                ldm_x4(bh[q], sb + T_BH + ro);
                ldm_x4(bl[q], sb + T_BL + ro);
            }
#pragma unroll
            for (int mf = 0; mf < 2; mf++)
#pragma unroll
                for (int nf = 0; nf < 8; nf++) {
                    const int q = nf >> 1, h = (nf & 1) * 2;
                    mma16816(acc[mf][nf], ah[mf], bh[q][h], bh[q][h + 1]);
                    mma16816(acc[mf][nf], al[mf], bh[q][h], bh[q][h + 1]);
                    mma16816(acc[mf][nf], ah[mf], bl[q][h], bl[q][h + 1]);
                }
        }
        __syncthreads();
    }

    // ---- epilogue ----
    const int tg = lane >> 2, tl = lane & 3;
#pragma unroll
    for (int mf = 0; mf < 2; mf++) {
#pragma unroll
        for (int nf = 0; nf < 8; nf++) {
            const int col = col0 + n0 + nf * 8 + tl * 2;
            float b0 = 0.f, b1 = 0.f;
            if (HASBIAS) { b0 = __ldg(bias + col); b1 = __ldg(bias + col + 1); }
#pragma unroll
            for (int hrow = 0; hrow < 2; hrow++) {
                const int row = row0 + m0 + mf * 16 + tg + hrow * 8;
                float v0 = acc[mf][nf][hrow * 2 + 0] * alpha + b0;
                float v1 = acc[mf][nf][hrow * 2 + 1] * alpha + b1;
                const long long off = zb * sC + (long long)row * N + col;
                if (WF32) {
                    float2 o; o.x = v0; o.y = v1;
                    *(float2*)(Cf + off) = o;
                } else {
                    __half h0 = __float2half_rn(v0);
                    __half h1 = __float2half_rn(v1);
                    __half2 th; th.x = h0; th.y = h1;
                    __half2 tlh;
                    tlh.x = __float2half_rn(v0 - __half2float(h0));
                    tlh.y = __float2half_rn(v1 - __half2float(h1));
                    *(__half2*)(Chi + off) = th;
                    *(__half2*)(Clo + off) = tlh;
                }
            }
        }
    }
}

// ============================================================================
// helper kernels
// ============================================================================
__global__ void __launch_bounds__(256) convert_split_kernel(
    const float* __restrict__ in, __half* __restrict__ hi,
    __half* __restrict__ lo, long long n4)
{
    long long i = (long long)blockIdx.x * 256 + threadIdx.x;
    if (i >= n4) return;
    float4 v = ((const float4*)in)[i];
    __half h0 = __float2half_rn(v.x), h1 = __float2half_rn(v.y);
    __half h2 = __float2half_rn(v.z), h3 = __float2half_rn(v.w);
    __half2 a, b; a.x = h0; a.y = h1; b.x = h2; b.y = h3;
    ((__half2*)hi)[i * 2 + 0] = a;
    ((__half2*)hi)[i * 2 + 1] = b;
    __half2 c, d;
    c.x = __float2half_rn(v.x - __half2float(h0));
    c.y = __float2half_rn(v.y - __half2float(h1));
    d.x = __float2half_rn(v.z - __half2float(h2));
    d.y = __float2half_rn(v.w - __half2float(h3));
    ((__half2*)lo)[i * 2 + 0] = c;
    ((__half2*)lo)[i * 2 + 1] = d;
}

// out[c][r] = in[r][c], split to fp16 hi/lo.
__global__ void __launch_bounds__(256) transpose_split_kernel(
    const float* __restrict__ in, __half* __restrict__ hi,
    __half* __restrict__ lo, int R, int C,
    long long sIn, long long sOut)
{
    __shared__ float t[32][33];
    const float* src = in + (long long)blockIdx.z * sIn;
    const int c0 = blockIdx.x * 32, r0 = blockIdx.y * 32;
    const int tx = threadIdx.x & 31, ty = threadIdx.x >> 5;
#pragma unroll
    for (int j = 0; j < 4; j++)
        t[ty + j * 8][tx] = src[(long long)(r0 + ty + j * 8) * C + c0 + tx];
    __syncthreads();
#pragma unroll
    for (int j = 0; j < 4; j++) {
        int oc = c0 + ty + j * 8;
        float v = t[tx][ty + j * 8];
        long long o = (long long)blockIdx.z * sOut + (long long)oc * R + r0 + tx;
        __half h = __float2half_rn(v);
        hi[o] = h;
        lo[o] = __float2half_rn(v - __half2float(h));
    }
}

// softmax rows of 2048 (fp32 in place) + fp16 hi/lo split output
__global__ void __launch_bounds__(256) softmax2048_kernel(
    float* __restrict__ p, __half* __restrict__ phi, __half* __restrict__ plo)
{
    const long long roff = (long long)blockIdx.x * 2048;
    float* row = p + roff;
    const int tid = threadIdx.x;

    float4 v0 = ((const float4*)row)[tid];
    float4 v1 = ((const float4*)row)[tid + 256];

    float m = fmaxf(fmaxf(fmaxf(v0.x, v0.y), fmaxf(v0.z, v0.w)),
                    fmaxf(fmaxf(v1.x, v1.y), fmaxf(v1.z, v1.w)));
    __shared__ float red[8];
#pragma unroll
    for (int o = 16; o; o >>= 1) m = fmaxf(m, __shfl_xor_sync(0xffffffffu, m, o));
    if ((tid & 31) == 0) red[tid >> 5] = m;
    __syncthreads();
    m = red[0];
#pragma unroll
    for (int i = 1; i < 8; i++) m = fmaxf(m, red[i]);
    __syncthreads();

    v0.x = expf(v0.x - m); v0.y = expf(v0.y - m);
    v0.z = expf(v0.z - m); v0.w = expf(v0.w - m);
    v1.x = expf(v1.x - m); v1.y = expf(v1.y - m);
    v1.z = expf(v1.z - m); v1.w = expf(v1.w - m);

    float s = (v0.x + v0.y) + (v0.z + v0.w) + (v1.x + v1.y) + (v1.z + v1.w);
#pragma unroll
    for (int o = 16; o; o >>= 1) s += __shfl_xor_sync(0xffffffffu, s, o);
    if ((tid & 31) == 0) red[tid >> 5] = s;
    __syncthreads();
    s = ((red[0] + red[1]) + (red[2] + red[3])) +
        ((red[4] + red[5]) + (red[6] + red[7]));
    float inv = 1.0f / s;

    v0.x *= inv; v0.y *= inv; v0.z *= inv; v0.w *= inv;
    v1.x *= inv; v1.y *= inv; v1.z *= inv; v1.w *= inv;

    ((float4*)row)[tid] = v0;
    ((float4*)row)[tid + 256] = v1;

    const float vv[8] = {v0.x, v0.y, v0.z, v0.w, v1.x, v1.y, v1.z, v1.w};
    const long long off[2] = {roff + (long long)tid * 4,
                              roff + (long long)(tid + 256) * 4};
#pragma unroll
    for (int hseg = 0; hseg < 2; hseg++) {
#pragma unroll
        for (int g = 0; g < 2; g++) {
            float a = vv[hseg * 4 + g * 2], b = vv[hseg * 4 + g * 2 + 1];
            __half ha = __float2half_rn(a), hb = __float2half_rn(b);
            __half2 th; th.x = ha; th.y = hb;
            __half2 tl;
            tl.x = __float2half_rn(a - __half2float(ha));
            tl.y = __float2half_rn(b - __half2float(hb));
            *(__half2*)(phi + off[hseg] + g * 2) = th;
            *(__half2*)(plo + off[hseg] + g * 2) = tl;
        }
    }
}

// ============================================================================
// host launcher
// ============================================================================
extern "C" void kernel_launch(void* const* d_in, const int* in_sizes, int n_in,
                              void* d_out, int out_size)
{
    const float* x  = (const float*)d_in[0];
    const float* wq = (const float*)d_in[1];
    const float* bq = (const float*)d_in[2];
    const float* wk = (const float*)d_in[3];
    const float* bk = (const float*)d_in[4];
    const float* wv = (const float*)d_in[5];
    const float* bv = (const float*)d_in[6];
    const float* wp = (const float*)d_in[7];
    const float* bp = (const float*)d_in[8];
    float* out = (float*)d_out;

#define SYM(p, s) void* p##_; cudaGetSymbolAddress(&p##_, s);
    SYM(xhi, g_xhi) SYM(xlo, g_xlo)
    SYM(wqh, g_wqThi) SYM(wql, g_wqTlo)
    SYM(wkh, g_wkThi) SYM(wkl, g_wkTlo)
    SYM(wvh, g_wvThi) SYM(wvl, g_wvTlo)
    SYM(wph, g_wpThi) SYM(wpl, g_wpTlo)
    SYM(qhi, g_qhi) SYM(qlo, g_qlo)
    SYM(khi, g_khi) SYM(klo, g_klo)
    SYM(vf, g_v)
    SYM(vth, g_vThi) SYM(vtl, g_vTlo)
    SYM(phi, g_phi) SYM(plo, g_plo)
    SYM(cxh, g_ctxhi) SYM(cxl, g_ctxlo)
    SYM(sfb, g_scores_fb)
#undef SYM
#define HF(p) ((__half*)p##_)

    float* pattn = (out_size >= (long long)(OUT_ELEMS + PATTN_ELEMS))
                       ? (out + OUT_ELEMS) : (float*)sfb_;

    cudaFuncSetAttribute(mma_gemm<false, true >, cudaFuncAttributeMaxDynamicSharedMemorySize, SMEM_DYN);
    cudaFuncSetAttribute(mma_gemm<false, false>, cudaFuncAttributeMaxDynamicSharedMemorySize, SMEM_DYN);
    cudaFuncSetAttribute(mma_gemm<true,  true >, cudaFuncAttributeMaxDynamicSharedMemorySize, SMEM_DYN);
    cudaFuncSetAttribute(mma_gemm<true,  false>, cudaFuncAttributeMaxDynamicSharedMemorySize, SMEM_DYN);

    // 1) split x
    convert_split_kernel<<<(TOK * DIM / 4 + 255) / 256, 256>>>(
        x, HF(xhi), HF(xlo), TOK * DIM / 4);

    // 2) transpose + split weights: wT[n][k] = w[k][n]
    dim3 gW(DIM / 32, DIM / 32, 1);
    transpose_split_kernel<<<gW, 256>>>(wq, HF(wqh), HF(wql), DIM, DIM, 0, 0);
    transpose_split_kernel<<<gW, 256>>>(wk, HF(wkh), HF(wkl), DIM, DIM, 0, 0);
    transpose_split_kernel<<<gW, 256>>>(wv, HF(wvh), HF(wvl), DIM, DIM, 0, 0);
    transpose_split_kernel<<<gW, 256>>>(wp, HF(wph), HF(wpl), DIM, DIM, 0, 0);

    // 3) q, k projections -> fp16 split outputs
    dim3 gProj(DIM / 128, TOK / 128, 1);
    mma_gemm<false, true><<<gProj, 256, SMEM_DYN>>>(
        HF(xhi), HF(xlo), HF(wqh), HF(wql), bq, nullptr, HF(qhi), HF(qlo),
        DIM, DIM, 1.f, 0, 0, 0);
    mma_gemm<false, true><<<gProj, 256, SMEM_DYN>>>(
        HF(xhi), HF(xlo), HF(wkh), HF(wkl), bk, nullptr, HF(khi), HF(klo),
        DIM, DIM, 1.f, 0, 0, 0);

    // 4) v projection -> fp32, then per-batch transpose-split -> vT[b][d][t]
    mma_gemm<true, true><<<gProj, 256, SMEM_DYN>>>(
        HF(xhi), HF(xlo), HF(wvh), HF(wvl), bv, (float*)vf_, nullptr, nullptr,
        DIM, DIM, 1.f, 0, 0, 0);
    dim3 gVT(DIM / 32, SEQ / 32, BATCH);
    transpose_split_kernel<<<gVT, 256>>>((const float*)vf_, HF(vth), HF(vtl),
                                         SEQ, DIM,
                                         (long long)SEQ * DIM, (long long)DIM * SEQ);

    // 5) scores = 32 * q @ k^T per batch -> fp32 p_attn region
    dim3 gSc(SEQ / 128, SEQ / 128, BATCH);
    mma_gemm<true, false><<<gSc, 256, SMEM_DYN>>>(
        HF(qhi), HF(qlo), HF(khi), HF(klo), nullptr, pattn, nullptr, nullptr,
        SEQ, DIM, 32.f,
        (long long)SEQ * DIM, (long long)SEQ * DIM, (long long)SEQ * SEQ);

    // 6) softmax in place + fp16 split of p
    softmax2048_kernel<<<TOK, 256>>>(pattn, HF(phi), HF(plo));

    // 7) ctx = p @ v per batch -> fp16 split
    dim3 gCtx(DIM / 128, SEQ / 128, BATCH);
    mma_gemm<false, false><<<gCtx, 256, SMEM_DYN>>>(
        HF(phi), HF(plo), HF(vth), HF(vtl), nullptr, nullptr, HF(cxh), HF(cxl),
        DIM, SEQ, 1.f,
        (long long)SEQ * SEQ, (long long)DIM * SEQ, (long long)SEQ * DIM);

    // 8) out = ctx @ wp + bp
    mma_gemm<true, true><<<gProj, 256, SMEM_DYN>>>(
        HF(cxh), HF(cxl), HF(wph), HF(wpl), bp, out, nullptr, nullptr,
        DIM, DIM, 1.f, 0, 0, 0);
}